// round 14
// baseline (speedup 1.0000x reference)
#include <cuda_runtime.h>
#include <cuda_fp16.h>

#define NN 100000
#define NE 1600000
#define F_HID 128
#define F_CLS 64
#define NBLK_SCAN 98               // ceil(NN/1024)
#define GB1 ((NN + 63) / 64)       // gemm1 64-row tiles = 1563
#define GB2 ((NN + 127) / 128)     // gemm2 128-row tiles = 782
#define ASTRIDE 136                // halfs per smem row (272B, LDSM conflict-free)
#define BSTRIDE 72                 // halfs per smem row for 64-wide W2 (144B)
#define FILL_GRID ((NE / 4 + 255) / 256)   // 1563 edge blocks

// ---- scratch (device globals; no allocs allowed) ----
__device__ int    g_cnt[2 * NN + 256];
__device__ int    g_row_ptr[NN + 1];
__device__ int    g_epos[NE];
__device__ int    g_csr_src[NE];
__device__ float  g_norm_in[NN];
__device__ float  g_norm_out[NN];
__device__ __half g_w1h[128 * F_HID];   // fp16 copy of W1
__device__ __half g_w2h[128 * F_CLS];   // fp16 copy of W2
__device__ __half g_t1[(size_t)NN * F_HID];
__device__ __half g_h [(size_t)NN * F_HID];
__device__ __half g_t2[(size_t)NN * F_CLS];

#define CNT_IN   (g_cnt)
#define CNT_OUT  (g_cnt + NN)
#define SCAN_VAL (g_cnt + 2 * NN)
#define SCAN_FLG (g_cnt + 2 * NN + 128)

// ---- fp16 vector load helpers ----
__device__ __forceinline__ void ldg_h4_f(const __half* p, float2& lo, float2& hi) {
    uint2 raw = __ldg((const uint2*)p);
    lo = __half22float2(*(const __half2*)&raw.x);
    hi = __half22float2(*(const __half2*)&raw.y);
}
__device__ __forceinline__ float2 ldg_h2_f(const __half* p) {
    unsigned int raw = __ldg((const unsigned int*)p);
    return __half22float2(*(const __half2*)&raw);
}

__device__ __forceinline__ int warp_incl_scan(int x, int lane) {
#pragma unroll
    for (int o = 1; o < 32; o <<= 1) {
        int y = __shfl_up_sync(0xffffffffu, x, o);
        if (lane >= o) x += y;
    }
    return x;
}

// ===========================================================================
// CSR build
// ===========================================================================
__global__ __launch_bounds__(256) void count_kernel(const int4* __restrict__ src4,
                                                    const int4* __restrict__ dst4) {
    int i = blockIdx.x * blockDim.x + threadIdx.x;
    if (i < NE / 4) {
        int4 s = __ldg(src4 + i);
        int4 d = __ldg(dst4 + i);
        atomicAdd(&CNT_OUT[s.x], 1); atomicAdd(&CNT_OUT[s.y], 1);
        atomicAdd(&CNT_OUT[s.z], 1); atomicAdd(&CNT_OUT[s.w], 1);
        int4 p;
        p.x = atomicAdd(&CNT_IN[d.x], 1);
        p.y = atomicAdd(&CNT_IN[d.y], 1);
        p.z = atomicAdd(&CNT_IN[d.z], 1);
        p.w = atomicAdd(&CNT_IN[d.w], 1);
        ((int4*)g_epos)[i] = p;
    }
}

// Single-pass scan with aggregate lookback (98 resident blocks).
__global__ __launch_bounds__(1024) void scan_onepass_kernel() {
    __shared__ int ws[32];
    __shared__ int s_base;
    int t = threadIdx.x, lane = t & 31, wid = t >> 5;
    int bid = blockIdx.x;

    int i = bid * 1024 + t;
    int v = (i < NN) ? CNT_IN[i] : 0;
    int x = warp_incl_scan(v, lane);
    if (lane == 31) ws[wid] = x;
    __syncthreads();
    if (wid == 0) ws[lane] = warp_incl_scan(ws[lane], lane);
    __syncthreads();
    int incl = x + (wid ? ws[wid - 1] : 0);
    int total = ws[31];

    if (t == 0) {
        SCAN_VAL[bid] = total;
        __threadfence();
        ((volatile int*)SCAN_FLG)[bid] = 1;
    }
    if (wid == 0) {
        int p = 0;
        for (int j = lane; j < bid; j += 32) {
            while (((volatile int*)SCAN_FLG)[j] == 0) { }
            p += ((volatile int*)SCAN_VAL)[j];
        }
        p = __reduce_add_sync(0xffffffffu, p);
        if (lane == 0) s_base = p;
    }
    __syncthreads();

    if (i < NN) {
        g_row_ptr[i] = incl - v + s_base;
        g_norm_in[i]  = rsqrtf(fmaxf((float)v, 1.0f));
        g_norm_out[i] = rsqrtf(fmaxf((float)CNT_OUT[i], 1.0f));
    }
    if (bid == 0 && t == 0) g_row_ptr[NN] = NE;
}

// fill: pure scatter, no atomics; two tail blocks convert W1/W2 -> fp16.
__global__ __launch_bounds__(256) void fill_kernel(const int4* __restrict__ src4,
                                                   const int4* __restrict__ dst4,
                                                   const float* __restrict__ W1,
                                                   const float* __restrict__ W2) {
    if (blockIdx.x == FILL_GRID) {        // W2 fp32 -> fp16 (8192 elems)
        int t = threadIdx.x;
        for (int i = t; i < 128 * F_CLS / 4; i += 256) {
            float4 v = __ldg(((const float4*)W2) + i);
            __half2 h01 = __floats2half2_rn(v.x, v.y);
            __half2 h23 = __floats2half2_rn(v.z, v.w);
            uint2 u = make_uint2(*(unsigned*)&h01, *(unsigned*)&h23);
            ((uint2*)g_w2h)[i] = u;
        }
        return;
    }
    if (blockIdx.x == FILL_GRID + 1) {    // W1 fp32 -> fp16 (16384 elems)
        int t = threadIdx.x;
        for (int i = t; i < 128 * F_HID / 4; i += 256) {
            float4 v = __ldg(((const float4*)W1) + i);
            __half2 h01 = __floats2half2_rn(v.x, v.y);
            __half2 h23 = __floats2half2_rn(v.z, v.w);
            uint2 u = make_uint2(*(unsigned*)&h01, *(unsigned*)&h23);
            ((uint2*)g_w1h)[i] = u;
        }
        return;
    }
    int i = blockIdx.x * blockDim.x + threadIdx.x;
    if (i < NE / 4) {
        int4 s = __ldg(src4 + i);
        int4 d = __ldg(dst4 + i);
        int4 p = ((const int4*)g_epos)[i];
        g_csr_src[__ldg(g_row_ptr + d.x) + p.x] = s.x;
        g_csr_src[__ldg(g_row_ptr + d.y) + p.y] = s.y;
        g_csr_src[__ldg(g_row_ptr + d.z) + p.z] = s.z;
        g_csr_src[__ldg(g_row_ptr + d.w) + p.w] = s.w;
    }
}

// ===========================================================================
// gemm1 (HMMA): t1[row] = half( (x[row] @ W1) * norm_out[row] )
// M-tile = 64 rows -> smem 52.2KB -> 4 blocks/SM. 8 warps = 4(M) x 2(N-half).
// W1 pre-converted fp16.
// ===========================================================================
__global__ __launch_bounds__(256)
void gemm1_mma_kernel(const float* __restrict__ X,
                      __half* __restrict__ Y) {
    extern __shared__ __half hsm[];
    __half* A_s = hsm;                    // [64][ASTRIDE]   17.4KB
    __half* B_s = hsm + 64 * ASTRIDE;     // [128][ASTRIDE]  34.8KB

    const int tid = threadIdx.x;
    const int row0 = blockIdx.x * 64;

    // W1h -> B_s (2048 uint2, pure copy)
    for (int i = tid; i < 128 * 32; i += 256) {
        int k = i >> 5, c8 = i & 31;
        uint2 u = __ldg(((const uint2*)g_w1h) + i);
        *((uint2*)(B_s + k * ASTRIDE + c8 * 4)) = u;
    }
    // X tile (64 rows fp32) -> A_s fp16
    for (int i = tid; i < 64 * 32; i += 256) {
        int r = i >> 5, c4 = i & 31;
        int row = row0 + r;
        float4 v = (row < NN)
            ? __ldg(((const float4*)(X + (size_t)row * 128)) + c4)
            : make_float4(0.f, 0.f, 0.f, 0.f);
        __half2 h01 = __floats2half2_rn(v.x, v.y);
        __half2 h23 = __floats2half2_rn(v.z, v.w);
        uint2 u = make_uint2(*(unsigned*)&h01, *(unsigned*)&h23);
        *((uint2*)(A_s + r * ASTRIDE + c4 * 4)) = u;
    }
    __syncthreads();

    const int w = tid >> 5, lane = tid & 31;
    const int wm = w & 3, wn = w >> 2;        // 4 M-strips x 2 N-halves
    const int mrow = wm * 16;
    const int ncol0 = wn * 64;

    float acc[8][4];
#pragma unroll
    for (int t = 0; t < 8; t++)
#pragma unroll
        for (int j = 0; j < 4; j++) acc[t][j] = 0.f;

#pragma unroll
    for (int ks = 0; ks < 8; ks++) {
        const int k0 = ks * 16;
        unsigned a0, a1, a2, a3;
        {
            const __half* pa = A_s + (mrow + (lane & 15)) * ASTRIDE
                             + k0 + (lane >> 4) * 8;
            unsigned addr = (unsigned)__cvta_generic_to_shared(pa);
            asm volatile("ldmatrix.sync.aligned.m8n8.x4.shared.b16 "
                         "{%0,%1,%2,%3}, [%4];"
                         : "=r"(a0), "=r"(a1), "=r"(a2), "=r"(a3) : "r"(addr));
        }
#pragma unroll
        for (int nt = 0; nt < 4; nt++) {
            unsigned b0, b1, b2, b3;
            const __half* pb = B_s + (k0 + (lane & 15)) * ASTRIDE
                             + ncol0 + nt * 16 + (lane >> 4) * 8;
            unsigned addr = (unsigned)__cvta_generic_to_shared(pb);
            asm volatile("ldmatrix.sync.aligned.m8n8.x4.trans.shared.b16 "
                         "{%0,%1,%2,%3}, [%4];"
                         : "=r"(b0), "=r"(b1), "=r"(b2), "=r"(b3) : "r"(addr));
            asm volatile("mma.sync.aligned.m16n8k16.row.col.f32.f16.f16.f32 "
                         "{%0,%1,%2,%3},{%4,%5,%6,%7},{%8,%9},{%0,%1,%2,%3};"
                         : "+f"(acc[nt*2][0]), "+f"(acc[nt*2][1]),
                           "+f"(acc[nt*2][2]), "+f"(acc[nt*2][3])
                         : "r"(a0), "r"(a1), "r"(a2), "r"(a3),
                           "r"(b0), "r"(b1));
            asm volatile("mma.sync.aligned.m16n8k16.row.col.f32.f16.f16.f32 "
                         "{%0,%1,%2,%3},{%4,%5,%6,%7},{%8,%9},{%0,%1,%2,%3};"
                         : "+f"(acc[nt*2+1][0]), "+f"(acc[nt*2+1][1]),
                           "+f"(acc[nt*2+1][2]), "+f"(acc[nt*2+1][3])
                         : "r"(a0), "r"(a1), "r"(a2), "r"(a3),
                           "r"(b2), "r"(b3));
        }
    }

    const int ra = row0 + mrow + (lane >> 2);
    const int rb = ra + 8;
    const float nsa = (ra < NN) ? __ldg(g_norm_out + ra) : 0.f;
    const float nsb = (rb < NN) ? __ldg(g_norm_out + rb) : 0.f;
    const int cbase = (lane & 3) * 2;
#pragma unroll
    for (int t = 0; t < 8; t++) {
        int c = ncol0 + t * 8 + cbase;
        if (ra < NN) {
            __half2 h = __floats2half2_rn(acc[t][0] * nsa, acc[t][1] * nsa);
            *((__half2*)(Y + (size_t)ra * 128 + c)) = h;
        }
        if (rb < NN) {
            __half2 h = __floats2half2_rn(acc[t][2] * nsb, acc[t][3] * nsb);
            *((__half2*)(Y + (size_t)rb * 128 + c)) = h;
        }
    }
}

// ===========================================================================
// gather128+relu: h[n] = half( relu(norm_in[n]*sum t1[csr] + b1) )
// ===========================================================================
__global__ __launch_bounds__(256)
void gather128_relu_kernel(const __half* __restrict__ T,
                           const float* __restrict__ b,
                           __half* __restrict__ out) {
    int w = (blockIdx.x * blockDim.x + threadIdx.x) >> 5;
    int lane = threadIdx.x & 31;
    if (w >= NN) return;
    int beg = g_row_ptr[w], end = g_row_ptr[w + 1];
    float4 acc = make_float4(0.f, 0.f, 0.f, 0.f);
    int i = beg;
    for (; i + 3 < end; i += 4) {
        int s0 = __ldg(g_csr_src + i),     s1 = __ldg(g_csr_src + i + 1);
        int s2 = __ldg(g_csr_src + i + 2), s3 = __ldg(g_csr_src + i + 3);
        float2 a0, c0, a1, c1, a2, c2, a3, c3;
        ldg_h4_f(T + (size_t)s0 * 128 + lane * 4, a0, c0);
        ldg_h4_f(T + (size_t)s1 * 128 + lane * 4, a1, c1);
        ldg_h4_f(T + (size_t)s2 * 128 + lane * 4, a2, c2);
        ldg_h4_f(T + (size_t)s3 * 128 + lane * 4, a3, c3);
        acc.x += (a0.x + a1.x) + (a2.x + a3.x);
        acc.y += (a0.y + a1.y) + (a2.y + a3.y);
        acc.z += (c0.x + c1.x) + (c2.x + c3.x);
        acc.w += (c0.y + c1.y) + (c2.y + c3.y);
    }
    for (; i < end; i++) {
        int s0 = __ldg(g_csr_src + i);
        float2 a0, c0;
        ldg_h4_f(T + (size_t)s0 * 128 + lane * 4, a0, c0);
        acc.x += a0.x; acc.y += a0.y; acc.z += c0.x; acc.w += c0.y;
    }
    float nd = g_norm_in[w];
    float4 bb = __ldg(((const float4*)b) + lane);
    float hx = fmaxf(fmaf(acc.x, nd, bb.x), 0.f);
    float hy = fmaxf(fmaf(acc.y, nd, bb.y), 0.f);
    float hz = fmaxf(fmaf(acc.z, nd, bb.z), 0.f);
    float hw = fmaxf(fmaf(acc.w, nd, bb.w), 0.f);
    __half2 o0 = __floats2half2_rn(hx, hy);
    __half2 o1 = __floats2half2_rn(hz, hw);
    uint2 u = make_uint2(*(unsigned*)&o0, *(unsigned*)&o1);
    ((uint2*)(out + (size_t)w * 128))[lane] = u;
}

// ===========================================================================
// gemm2 (HMMA): t2[row] = half( (h[row] @ W2) * norm_out[row] )   N=64
// ===========================================================================
__global__ __launch_bounds__(256)
void gemm2_mma_kernel(const __half* __restrict__ H,
                      __half* __restrict__ Y) {
    extern __shared__ __half hsm[];
    __half* A_s = hsm;                    // [128][ASTRIDE]  ~34.8KB
    __half* B_s = hsm + 128 * ASTRIDE;    // [128][BSTRIDE]  ~9.2KB

    const int tid = threadIdx.x;
    const int row0 = blockIdx.x * 128;

    for (int i = tid; i < 128 * 16; i += 256) {
        int k = i >> 4, c4 = i & 15;
        uint2 u = __ldg(((const uint2*)g_w2h) + i);
        *((uint2*)(B_s + k * BSTRIDE + c4 * 4)) = u;
    }
    for (int i = tid; i < 128 * 32; i += 256) {
        int r = i >> 5, c8 = i & 31;
        int row = row0 + r;
        uint2 u = (row < NN)
            ? __ldg(((const uint2*)(H + (size_t)row * 128)) + c8)
            : make_uint2(0u, 0u);
        *((uint2*)(A_s + r * ASTRIDE + c8 * 4)) = u;
    }
    __syncthreads();

    const int w = tid >> 5, lane = tid & 31;
    const int mrow = w * 16;

    float acc[8][4];
#pragma unroll
    for (int t = 0; t < 8; t++)
#pragma unroll
        for (int j = 0; j < 4; j++) acc[t][j] = 0.f;

#pragma unroll
    for (int ks = 0; ks < 8; ks++) {
        const int k0 = ks * 16;
        unsigned a0, a1, a2, a3;
        {
            const __half* pa = A_s + (mrow + (lane & 15)) * ASTRIDE
                             + k0 + (lane >> 4) * 8;
            unsigned addr = (unsigned)__cvta_generic_to_shared(pa);
            asm volatile("ldmatrix.sync.aligned.m8n8.x4.shared.b16 "
                         "{%0,%1,%2,%3}, [%4];"
                         : "=r"(a0), "=r"(a1), "=r"(a2), "=r"(a3) : "r"(addr));
        }
#pragma unroll
        for (int nt = 0; nt < 4; nt++) {
            unsigned b0, b1, b2, b3;
            const __half* pb = B_s + (k0 + (lane & 15)) * BSTRIDE
                             + nt * 16 + (lane >> 4) * 8;
            unsigned addr = (unsigned)__cvta_generic_to_shared(pb);
            asm volatile("ldmatrix.sync.aligned.m8n8.x4.trans.shared.b16 "
                         "{%0,%1,%2,%3}, [%4];"
                         : "=r"(b0), "=r"(b1), "=r"(b2), "=r"(b3) : "r"(addr));
            asm volatile("mma.sync.aligned.m16n8k16.row.col.f32.f16.f16.f32 "
                         "{%0,%1,%2,%3},{%4,%5,%6,%7},{%8,%9},{%0,%1,%2,%3};"
                         : "+f"(acc[nt*2][0]), "+f"(acc[nt*2][1]),
                           "+f"(acc[nt*2][2]), "+f"(acc[nt*2][3])
                         : "r"(a0), "r"(a1), "r"(a2), "r"(a3),
                           "r"(b0), "r"(b1));
            asm volatile("mma.sync.aligned.m16n8k16.row.col.f32.f16.f16.f32 "
                         "{%0,%1,%2,%3},{%4,%5,%6,%7},{%8,%9},{%0,%1,%2,%3};"
                         : "+f"(acc[nt*2+1][0]), "+f"(acc[nt*2+1][1]),
                           "+f"(acc[nt*2+1][2]), "+f"(acc[nt*2+1][3])
                         : "r"(a0), "r"(a1), "r"(a2), "r"(a3),
                           "r"(b2), "r"(b3));
        }
    }

    const int ra = row0 + mrow + (lane >> 2);
    const int rb = ra + 8;
    const float nsa = (ra < NN) ? __ldg(g_norm_out + ra) : 0.f;
    const float nsb = (rb < NN) ? __ldg(g_norm_out + rb) : 0.f;
    const int cbase = (lane & 3) * 2;
#pragma unroll
    for (int t = 0; t < 8; t++) {
        int c = t * 8 + cbase;
        if (ra < NN) {
            __half2 h = __floats2half2_rn(acc[t][0] * nsa, acc[t][1] * nsa);
            *((__half2*)(Y + (size_t)ra * 64 + c)) = h;
        }
        if (rb < NN) {
            __half2 h = __floats2half2_rn(acc[t][2] * nsb, acc[t][3] * nsb);
            *((__half2*)(Y + (size_t)rb * 64 + c)) = h;
        }
    }
}

// ===========================================================================
// Final gather: out[n] = norm_in[n] * sum t2[csr] + b2
// ===========================================================================
__global__ __launch_bounds__(256)
void gather64_kernel(const __half* __restrict__ T,
                     const float* __restrict__ b,
                     float* __restrict__ out) {
    int w = (blockIdx.x * blockDim.x + threadIdx.x) >> 5;
    int lane = threadIdx.x & 31;
    if (w >= NN) return;
    int beg = g_row_ptr[w], end = g_row_ptr[w + 1];
    float2 acc = make_float2(0.f, 0.f);
    int i = beg;
    for (; i + 3 < end; i += 4) {
        int s0 = __ldg(g_csr_src + i),     s1 = __ldg(g_csr_src + i + 1);
        int s2 = __ldg(g_csr_src + i + 2), s3 = __ldg(g_csr_src + i + 3);
        float2 f0 = ldg_h2_f(T + (size_t)s0 * 64 + lane * 2);
        float2 f1 = ldg_h2_f(T + (size_t)s1 * 64 + lane * 2);
        float2 f2 = ldg_h2_f(T + (size_t)s2 * 64 + lane * 2);
        float2 f3 = ldg_h2_f(T + (size_t)s3 * 64 + lane * 2);
        acc.x += (f0.x + f1.x) + (f2.x + f3.x);
        acc.y += (f0.y + f1.y) + (f2.y + f3.y);
    }
    for (; i < end; i++) {
        int s0 = __ldg(g_csr_src + i);
        float2 f0 = ldg_h2_f(T + (size_t)s0 * 64 + lane * 2);
        acc.x += f0.x; acc.y += f0.y;
    }
    float nd = g_norm_in[w];
    float2 bb = __ldg(((const float2*)b) + lane);
    float2 o;
    o.x = fmaf(acc.x, nd, bb.x);
    o.y = fmaf(acc.y, nd, bb.y);
    ((float2*)(out + (size_t)w * 64))[lane] = o;
}

// ===========================================================================
extern "C" void kernel_launch(void* const* d_in, const int* in_sizes, int n_in,
                              void* d_out, int out_size) {
    const float* x   = (const float*)d_in[0];
    const int*   src = (const int*)d_in[1];
    const int*   dst = (const int*)d_in[2];
    const float* W1  = (const float*)d_in[3];
    const float* b1  = (const float*)d_in[4];
    const float* W2  = (const float*)d_in[5];
    const float* b2  = (const float*)d_in[6];
    float* out = (float*)d_out;

    void *p_t1, *p_t2, *p_h, *p_cnt;
    cudaGetSymbolAddress(&p_t1, g_t1);
    cudaGetSymbolAddress(&p_t2, g_t2);
    cudaGetSymbolAddress(&p_h,  g_h);
    cudaGetSymbolAddress(&p_cnt, g_cnt);

    size_t sm1 = (size_t)((64 + 128) * ASTRIDE) * sizeof(__half);   // ~52.2KB
    cudaFuncSetAttribute(gemm1_mma_kernel,
                         cudaFuncAttributeMaxDynamicSharedMemorySize, (int)sm1);
    size_t sm2 = (size_t)(128 * ASTRIDE + 128 * BSTRIDE) * sizeof(__half); // ~44KB
    cudaFuncSetAttribute(gemm2_mma_kernel,
                         cudaFuncAttributeMaxDynamicSharedMemorySize, (int)sm2);

    cudaMemsetAsync(p_cnt, 0, (2 * NN + 256) * sizeof(int));
    count_kernel<<<(NE / 4 + 255) / 256, 256>>>((const int4*)src, (const int4*)dst);
    scan_onepass_kernel<<<NBLK_SCAN, 1024>>>();
    fill_kernel<<<FILL_GRID + 2, 256>>>((const int4*)src, (const int4*)dst, W1, W2);

    gemm1_mma_kernel<<<GB1, 256, sm1>>>(x, (__half*)p_t1);

    gather128_relu_kernel<<<(NN * 32 + 255) / 256, 256>>>(
        (const __half*)p_t1, b1, (__half*)p_h);

    gemm2_mma_kernel<<<GB2, 256, sm2>>>((const __half*)p_h, (__half*)p_t2);

    gather64_kernel<<<(NN * 32 + 255) / 256, 256>>>(
        (const __half*)p_t2, b2, out);
}

// round 15
// speedup vs baseline: 1.0427x; 1.0427x over previous
#include <cuda_runtime.h>
#include <cuda_fp16.h>

#define NN 100000
#define NE 1600000
#define F_HID 128
#define F_CLS 64
#define NBLK_SCAN 98               // ceil(NN/1024)
#define GB ((NN + 127) / 128)      // 128-row tiles = 782
#define ASTRIDE 136                // halfs per smem row (272B, LDSM conflict-free)
#define BSTRIDE 72                 // halfs per smem row for 64-wide W2 (144B)
#define FILL_GRID ((NE / 4 + 255) / 256)   // 1563 edge blocks

// ---- scratch (device globals; no allocs allowed) ----
__device__ int    g_cnt[2 * NN + 256];
__device__ int    g_row_ptr[NN + 1];
__device__ int    g_epos[NE];
__device__ int    g_csr_src[NE];
__device__ float  g_norm_in[NN];
__device__ float  g_norm_out[NN];
__device__ __half g_w1h[128 * F_HID];   // fp16 copy of W1
__device__ __half g_w2h[128 * F_CLS];   // fp16 copy of W2
__device__ __half g_t1[(size_t)NN * F_HID];
__device__ __half g_h [(size_t)NN * F_HID];
__device__ __half g_t2[(size_t)NN * F_CLS];

#define CNT_IN   (g_cnt)
#define CNT_OUT  (g_cnt + NN)
#define SCAN_VAL (g_cnt + 2 * NN)
#define SCAN_FLG (g_cnt + 2 * NN + 128)

// ---- fp16 vector load helpers ----
__device__ __forceinline__ void ldg_h4_f(const __half* p, float2& lo, float2& hi) {
    uint2 raw = __ldg((const uint2*)p);
    lo = __half22float2(*(const __half2*)&raw.x);
    hi = __half22float2(*(const __half2*)&raw.y);
}
__device__ __forceinline__ float2 ldg_h2_f(const __half* p) {
    unsigned int raw = __ldg((const unsigned int*)p);
    return __half22float2(*(const __half2*)&raw);
}

__device__ __forceinline__ int warp_incl_scan(int x, int lane) {
#pragma unroll
    for (int o = 1; o < 32; o <<= 1) {
        int y = __shfl_up_sync(0xffffffffu, x, o);
        if (lane >= o) x += y;
    }
    return x;
}

// ===========================================================================
// CSR build
// ===========================================================================
__global__ __launch_bounds__(256) void count_kernel(const int4* __restrict__ src4,
                                                    const int4* __restrict__ dst4) {
    int i = blockIdx.x * blockDim.x + threadIdx.x;
    if (i < NE / 4) {
        int4 s = __ldg(src4 + i);
        int4 d = __ldg(dst4 + i);
        atomicAdd(&CNT_OUT[s.x], 1); atomicAdd(&CNT_OUT[s.y], 1);
        atomicAdd(&CNT_OUT[s.z], 1); atomicAdd(&CNT_OUT[s.w], 1);
        int4 p;
        p.x = atomicAdd(&CNT_IN[d.x], 1);
        p.y = atomicAdd(&CNT_IN[d.y], 1);
        p.z = atomicAdd(&CNT_IN[d.z], 1);
        p.w = atomicAdd(&CNT_IN[d.w], 1);
        ((int4*)g_epos)[i] = p;
    }
}

// Single-pass scan with aggregate lookback (98 resident blocks).
__global__ __launch_bounds__(1024) void scan_onepass_kernel() {
    __shared__ int ws[32];
    __shared__ int s_base;
    int t = threadIdx.x, lane = t & 31, wid = t >> 5;
    int bid = blockIdx.x;

    int i = bid * 1024 + t;
    int v = (i < NN) ? CNT_IN[i] : 0;
    int x = warp_incl_scan(v, lane);
    if (lane == 31) ws[wid] = x;
    __syncthreads();
    if (wid == 0) ws[lane] = warp_incl_scan(ws[lane], lane);
    __syncthreads();
    int incl = x + (wid ? ws[wid - 1] : 0);
    int total = ws[31];

    if (t == 0) {
        SCAN_VAL[bid] = total;
        __threadfence();
        ((volatile int*)SCAN_FLG)[bid] = 1;
    }
    if (wid == 0) {
        int p = 0;
        for (int j = lane; j < bid; j += 32) {
            while (((volatile int*)SCAN_FLG)[j] == 0) { }
            p += ((volatile int*)SCAN_VAL)[j];
        }
        p = __reduce_add_sync(0xffffffffu, p);
        if (lane == 0) s_base = p;
    }
    __syncthreads();

    if (i < NN) {
        g_row_ptr[i] = incl - v + s_base;
        g_norm_in[i]  = rsqrtf(fmaxf((float)v, 1.0f));
        g_norm_out[i] = rsqrtf(fmaxf((float)CNT_OUT[i], 1.0f));
    }
    if (bid == 0 && t == 0) g_row_ptr[NN] = NE;
}

// fill: pure scatter, no atomics; two tail blocks convert W1/W2 -> fp16.
__global__ __launch_bounds__(256) void fill_kernel(const int4* __restrict__ src4,
                                                   const int4* __restrict__ dst4,
                                                   const float* __restrict__ W1,
                                                   const float* __restrict__ W2) {
    if (blockIdx.x == FILL_GRID) {        // W2 fp32 -> fp16
        int t = threadIdx.x;
        for (int i = t; i < 128 * F_CLS / 4; i += 256) {
            float4 v = __ldg(((const float4*)W2) + i);
            __half2 h01 = __floats2half2_rn(v.x, v.y);
            __half2 h23 = __floats2half2_rn(v.z, v.w);
            uint2 u = make_uint2(*(unsigned*)&h01, *(unsigned*)&h23);
            ((uint2*)g_w2h)[i] = u;
        }
        return;
    }
    if (blockIdx.x == FILL_GRID + 1) {    // W1 fp32 -> fp16
        int t = threadIdx.x;
        for (int i = t; i < 128 * F_HID / 4; i += 256) {
            float4 v = __ldg(((const float4*)W1) + i);
            __half2 h01 = __floats2half2_rn(v.x, v.y);
            __half2 h23 = __floats2half2_rn(v.z, v.w);
            uint2 u = make_uint2(*(unsigned*)&h01, *(unsigned*)&h23);
            ((uint2*)g_w1h)[i] = u;
        }
        return;
    }
    int i = blockIdx.x * blockDim.x + threadIdx.x;
    if (i < NE / 4) {
        int4 s = __ldg(src4 + i);
        int4 d = __ldg(dst4 + i);
        int4 p = ((const int4*)g_epos)[i];
        g_csr_src[__ldg(g_row_ptr + d.x) + p.x] = s.x;
        g_csr_src[__ldg(g_row_ptr + d.y) + p.y] = s.y;
        g_csr_src[__ldg(g_row_ptr + d.z) + p.z] = s.z;
        g_csr_src[__ldg(g_row_ptr + d.w) + p.w] = s.w;
    }
}

// ===========================================================================
// gemm1 (HMMA): t1[row] = half( (x[row] @ W1) * norm_out[row] )
// 128-row tile, 8 warps x 16 rows, coalesced smem-staged epilogue.
// ===========================================================================
__global__ __launch_bounds__(256)
void gemm1_mma_kernel(const float* __restrict__ X,
                      __half* __restrict__ Y) {
    extern __shared__ __half hsm[];
    __half* A_s = hsm;                    // [128][ASTRIDE]
    __half* B_s = hsm + 128 * ASTRIDE;    // [128][ASTRIDE]

    const int tid = threadIdx.x;
    const int row0 = blockIdx.x * 128;

    // W1h -> B_s (pure uint2 copy)
    for (int i = tid; i < 128 * 32; i += 256) {
        int k = i >> 5, c8 = i & 31;
        uint2 u = __ldg(((const uint2*)g_w1h) + i);
        *((uint2*)(B_s + k * ASTRIDE + c8 * 4)) = u;
    }
    // X tile (fp32) -> A_s fp16
    for (int i = tid; i < 128 * 32; i += 256) {
        int r = i >> 5, c4 = i & 31;
        int row = row0 + r;
        float4 v = (row < NN)
            ? __ldg(((const float4*)(X + (size_t)row * 128)) + c4)
            : make_float4(0.f, 0.f, 0.f, 0.f);
        __half2 h01 = __floats2half2_rn(v.x, v.y);
        __half2 h23 = __floats2half2_rn(v.z, v.w);
        uint2 u = make_uint2(*(unsigned*)&h01, *(unsigned*)&h23);
        *((uint2*)(A_s + r * ASTRIDE + c4 * 4)) = u;
    }
    __syncthreads();

    const int w = tid >> 5, lane = tid & 31;
    const int mrow = w * 16;

    float acc[16][4];
#pragma unroll
    for (int t = 0; t < 16; t++)
#pragma unroll
        for (int j = 0; j < 4; j++) acc[t][j] = 0.f;

#pragma unroll
    for (int ks = 0; ks < 8; ks++) {
        const int k0 = ks * 16;
        unsigned a0, a1, a2, a3;
        {
            const __half* pa = A_s + (mrow + (lane & 15)) * ASTRIDE
                             + k0 + (lane >> 4) * 8;
            unsigned addr = (unsigned)__cvta_generic_to_shared(pa);
            asm volatile("ldmatrix.sync.aligned.m8n8.x4.shared.b16 "
                         "{%0,%1,%2,%3}, [%4];"
                         : "=r"(a0), "=r"(a1), "=r"(a2), "=r"(a3) : "r"(addr));
        }
#pragma unroll
        for (int nt = 0; nt < 8; nt++) {
            unsigned b0, b1, b2, b3;
            const __half* pb = B_s + (k0 + (lane & 15)) * ASTRIDE
                             + nt * 16 + (lane >> 4) * 8;
            unsigned addr = (unsigned)__cvta_generic_to_shared(pb);
            asm volatile("ldmatrix.sync.aligned.m8n8.x4.trans.shared.b16 "
                         "{%0,%1,%2,%3}, [%4];"
                         : "=r"(b0), "=r"(b1), "=r"(b2), "=r"(b3) : "r"(addr));
            asm volatile("mma.sync.aligned.m16n8k16.row.col.f32.f16.f16.f32 "
                         "{%0,%1,%2,%3},{%4,%5,%6,%7},{%8,%9},{%0,%1,%2,%3};"
                         : "+f"(acc[nt*2][0]), "+f"(acc[nt*2][1]),
                           "+f"(acc[nt*2][2]), "+f"(acc[nt*2][3])
                         : "r"(a0), "r"(a1), "r"(a2), "r"(a3),
                           "r"(b0), "r"(b1));
            asm volatile("mma.sync.aligned.m16n8k16.row.col.f32.f16.f16.f32 "
                         "{%0,%1,%2,%3},{%4,%5,%6,%7},{%8,%9},{%0,%1,%2,%3};"
                         : "+f"(acc[nt*2+1][0]), "+f"(acc[nt*2+1][1]),
                           "+f"(acc[nt*2+1][2]), "+f"(acc[nt*2+1][3])
                         : "r"(a0), "r"(a1), "r"(a2), "r"(a3),
                           "r"(b2), "r"(b3));
        }
    }

    // Staged epilogue: scatter (scaled fp16) into A_s, then coalesced STG.128.
    __syncthreads();   // all ldmatrix reads done; A_s reusable
    {
        const int rla = mrow + (lane >> 2);
        const int rlb = rla + 8;
        const float nsa = (row0 + rla < NN) ? __ldg(g_norm_out + row0 + rla) : 0.f;
        const float nsb = (row0 + rlb < NN) ? __ldg(g_norm_out + row0 + rlb) : 0.f;
        const int cbase = (lane & 3) * 2;
#pragma unroll
        for (int t = 0; t < 16; t++) {
            int c = t * 8 + cbase;
            *((__half2*)(A_s + rla * ASTRIDE + c)) =
                __floats2half2_rn(acc[t][0] * nsa, acc[t][1] * nsa);
            *((__half2*)(A_s + rlb * ASTRIDE + c)) =
                __floats2half2_rn(acc[t][2] * nsb, acc[t][3] * nsb);
        }
    }
    __syncthreads();
    // 128 rows x 16 uint4 per row = 2048 STG.128, coalesced
    for (int i = tid; i < 128 * 16; i += 256) {
        int r = i >> 4, ch = i & 15;
        int row = row0 + r;
        if (row < NN) {
            uint4 u = *((const uint4*)(A_s + r * ASTRIDE + ch * 8));
            ((uint4*)(Y + (size_t)row * 128))[ch] = u;
        }
    }
}

// ===========================================================================
// gather128+relu: h[n] = half( relu(norm_in[n]*sum t1[csr] + b1) )
// ===========================================================================
__global__ __launch_bounds__(256)
void gather128_relu_kernel(const __half* __restrict__ T,
                           const float* __restrict__ b,
                           __half* __restrict__ out) {
    int w = (blockIdx.x * blockDim.x + threadIdx.x) >> 5;
    int lane = threadIdx.x & 31;
    if (w >= NN) return;
    int beg = g_row_ptr[w], end = g_row_ptr[w + 1];
    float4 acc = make_float4(0.f, 0.f, 0.f, 0.f);
    int i = beg;
    for (; i + 3 < end; i += 4) {
        int s0 = __ldg(g_csr_src + i),     s1 = __ldg(g_csr_src + i + 1);
        int s2 = __ldg(g_csr_src + i + 2), s3 = __ldg(g_csr_src + i + 3);
        float2 a0, c0, a1, c1, a2, c2, a3, c3;
        ldg_h4_f(T + (size_t)s0 * 128 + lane * 4, a0, c0);
        ldg_h4_f(T + (size_t)s1 * 128 + lane * 4, a1, c1);
        ldg_h4_f(T + (size_t)s2 * 128 + lane * 4, a2, c2);
        ldg_h4_f(T + (size_t)s3 * 128 + lane * 4, a3, c3);
        acc.x += (a0.x + a1.x) + (a2.x + a3.x);
        acc.y += (a0.y + a1.y) + (a2.y + a3.y);
        acc.z += (c0.x + c1.x) + (c2.x + c3.x);
        acc.w += (c0.y + c1.y) + (c2.y + c3.y);
    }
    for (; i < end; i++) {
        int s0 = __ldg(g_csr_src + i);
        float2 a0, c0;
        ldg_h4_f(T + (size_t)s0 * 128 + lane * 4, a0, c0);
        acc.x += a0.x; acc.y += a0.y; acc.z += c0.x; acc.w += c0.y;
    }
    float nd = g_norm_in[w];
    float4 bb = __ldg(((const float4*)b) + lane);
    float hx = fmaxf(fmaf(acc.x, nd, bb.x), 0.f);
    float hy = fmaxf(fmaf(acc.y, nd, bb.y), 0.f);
    float hz = fmaxf(fmaf(acc.z, nd, bb.z), 0.f);
    float hw = fmaxf(fmaf(acc.w, nd, bb.w), 0.f);
    __half2 o0 = __floats2half2_rn(hx, hy);
    __half2 o1 = __floats2half2_rn(hz, hw);
    uint2 u = make_uint2(*(unsigned*)&o0, *(unsigned*)&o1);
    ((uint2*)(out + (size_t)w * 128))[lane] = u;
}

// ===========================================================================
// gemm2 (HMMA): t2[row] = half( (h[row] @ W2) * norm_out[row] )   N=64
// Coalesced smem-staged epilogue.
// ===========================================================================
__global__ __launch_bounds__(256)
void gemm2_mma_kernel(const __half* __restrict__ H,
                      __half* __restrict__ Y) {
    extern __shared__ __half hsm[];
    __half* A_s = hsm;                    // [128][ASTRIDE]
    __half* B_s = hsm + 128 * ASTRIDE;    // [128][BSTRIDE]

    const int tid = threadIdx.x;
    const int row0 = blockIdx.x * 128;

    for (int i = tid; i < 128 * 16; i += 256) {
        int k = i >> 4, c4 = i & 15;
        uint2 u = __ldg(((const uint2*)g_w2h) + i);
        *((uint2*)(B_s + k * BSTRIDE + c4 * 4)) = u;
    }
    for (int i = tid; i < 128 * 32; i += 256) {
        int r = i >> 5, c8 = i & 31;
        int row = row0 + r;
        uint2 u = (row < NN)
            ? __ldg(((const uint2*)(H + (size_t)row * 128)) + c8)
            : make_uint2(0u, 0u);
        *((uint2*)(A_s + r * ASTRIDE + c8 * 4)) = u;
    }
    __syncthreads();

    const int w = tid >> 5, lane = tid & 31;
    const int mrow = w * 16;

    float acc[8][4];
#pragma unroll
    for (int t = 0; t < 8; t++)
#pragma unroll
        for (int j = 0; j < 4; j++) acc[t][j] = 0.f;

#pragma unroll
    for (int ks = 0; ks < 8; ks++) {
        const int k0 = ks * 16;
        unsigned a0, a1, a2, a3;
        {
            const __half* pa = A_s + (mrow + (lane & 15)) * ASTRIDE
                             + k0 + (lane >> 4) * 8;
            unsigned addr = (unsigned)__cvta_generic_to_shared(pa);
            asm volatile("ldmatrix.sync.aligned.m8n8.x4.shared.b16 "
                         "{%0,%1,%2,%3}, [%4];"
                         : "=r"(a0), "=r"(a1), "=r"(a2), "=r"(a3) : "r"(addr));
        }
#pragma unroll
        for (int nt = 0; nt < 4; nt++) {
            unsigned b0, b1, b2, b3;
            const __half* pb = B_s + (k0 + (lane & 15)) * BSTRIDE
                             + nt * 16 + (lane >> 4) * 8;
            unsigned addr = (unsigned)__cvta_generic_to_shared(pb);
            asm volatile("ldmatrix.sync.aligned.m8n8.x4.trans.shared.b16 "
                         "{%0,%1,%2,%3}, [%4];"
                         : "=r"(b0), "=r"(b1), "=r"(b2), "=r"(b3) : "r"(addr));
            asm volatile("mma.sync.aligned.m16n8k16.row.col.f32.f16.f16.f32 "
                         "{%0,%1,%2,%3},{%4,%5,%6,%7},{%8,%9},{%0,%1,%2,%3};"
                         : "+f"(acc[nt*2][0]), "+f"(acc[nt*2][1]),
                           "+f"(acc[nt*2][2]), "+f"(acc[nt*2][3])
                         : "r"(a0), "r"(a1), "r"(a2), "r"(a3),
                           "r"(b0), "r"(b1));
            asm volatile("mma.sync.aligned.m16n8k16.row.col.f32.f16.f16.f32 "
                         "{%0,%1,%2,%3},{%4,%5,%6,%7},{%8,%9},{%0,%1,%2,%3};"
                         : "+f"(acc[nt*2+1][0]), "+f"(acc[nt*2+1][1]),
                           "+f"(acc[nt*2+1][2]), "+f"(acc[nt*2+1][3])
                         : "r"(a0), "r"(a1), "r"(a2), "r"(a3),
                           "r"(b2), "r"(b3));
        }
    }

    // Staged epilogue (output tile 128 x 64 halfs into A_s, then STG.128)
    __syncthreads();
    {
        const int rla = mrow + (lane >> 2);
        const int rlb = rla + 8;
        const float nsa = (row0 + rla < NN) ? __ldg(g_norm_out + row0 + rla) : 0.f;
        const float nsb = (row0 + rlb < NN) ? __ldg(g_norm_out + row0 + rlb) : 0.f;
        const int cbase = (lane & 3) * 2;
#pragma unroll
        for (int t = 0; t < 8; t++) {
            int c = t * 8 + cbase;
            *((__half2*)(A_s + rla * ASTRIDE + c)) =
                __floats2half2_rn(acc[t][0] * nsa, acc[t][1] * nsa);
            *((__half2*)(A_s + rlb * ASTRIDE + c)) =
                __floats2half2_rn(acc[t][2] * nsb, acc[t][3] * nsb);
        }
    }
    __syncthreads();
    // 128 rows x 8 uint4 per row = 1024 STG.128, coalesced
    for (int i = tid; i < 128 * 8; i += 256) {
        int r = i >> 3, ch = i & 7;
        int row = row0 + r;
        if (row < NN) {
            uint4 u = *((const uint4*)(A_s + r * ASTRIDE + ch * 8));
            ((uint4*)(Y + (size_t)row * 64))[ch] = u;
        }
    }
}

// ===========================================================================
// Final gather: out[n] = norm_in[n] * sum t2[csr] + b2
// ===========================================================================
__global__ __launch_bounds__(256)
void gather64_kernel(const __half* __restrict__ T,
                     const float* __restrict__ b,
                     float* __restrict__ out) {
    int w = (blockIdx.x * blockDim.x + threadIdx.x) >> 5;
    int lane = threadIdx.x & 31;
    if (w >= NN) return;
    int beg = g_row_ptr[w], end = g_row_ptr[w + 1];
    float2 acc = make_float2(0.f, 0.f);
    int i = beg;
    for (; i + 3 < end; i += 4) {
        int s0 = __ldg(g_csr_src + i),     s1 = __ldg(g_csr_src + i + 1);
        int s2 = __ldg(g_csr_src + i + 2), s3 = __ldg(g_csr_src + i + 3);
        float2 f0 = ldg_h2_f(T + (size_t)s0 * 64 + lane * 2);
        float2 f1 = ldg_h2_f(T + (size_t)s1 * 64 + lane * 2);
        float2 f2 = ldg_h2_f(T + (size_t)s2 * 64 + lane * 2);
        float2 f3 = ldg_h2_f(T + (size_t)s3 * 64 + lane * 2);
        acc.x += (f0.x + f1.x) + (f2.x + f3.x);
        acc.y += (f0.y + f1.y) + (f2.y + f3.y);
    }
    for (; i < end; i++) {
        int s0 = __ldg(g_csr_src + i);
        float2 f0 = ldg_h2_f(T + (size_t)s0 * 64 + lane * 2);
        acc.x += f0.x; acc.y += f0.y;
    }
    float nd = g_norm_in[w];
    float2 bb = __ldg(((const float2*)b) + lane);
    float2 o;
    o.x = fmaf(acc.x, nd, bb.x);
    o.y = fmaf(acc.y, nd, bb.y);
    ((float2*)(out + (size_t)w * 64))[lane] = o;
}

// ===========================================================================
extern "C" void kernel_launch(void* const* d_in, const int* in_sizes, int n_in,
                              void* d_out, int out_size) {
    const float* x   = (const float*)d_in[0];
    const int*   src = (const int*)d_in[1];
    const int*   dst = (const int*)d_in[2];
    const float* W1  = (const float*)d_in[3];
    const float* b1  = (const float*)d_in[4];
    const float* W2  = (const float*)d_in[5];
    const float* b2  = (const float*)d_in[6];
    float* out = (float*)d_out;

    void *p_t1, *p_t2, *p_h, *p_cnt;
    cudaGetSymbolAddress(&p_t1, g_t1);
    cudaGetSymbolAddress(&p_t2, g_t2);
    cudaGetSymbolAddress(&p_h,  g_h);
    cudaGetSymbolAddress(&p_cnt, g_cnt);

    size_t sm1 = (size_t)(2 * 128 * ASTRIDE) * sizeof(__half);   // ~68KB
    cudaFuncSetAttribute(gemm1_mma_kernel,
                         cudaFuncAttributeMaxDynamicSharedMemorySize, (int)sm1);
    size_t sm2 = (size_t)(128 * ASTRIDE + 128 * BSTRIDE) * sizeof(__half); // ~44KB
    cudaFuncSetAttribute(gemm2_mma_kernel,
                         cudaFuncAttributeMaxDynamicSharedMemorySize, (int)sm2);

    cudaMemsetAsync(p_cnt, 0, (2 * NN + 256) * sizeof(int));
    count_kernel<<<(NE / 4 + 255) / 256, 256>>>((const int4*)src, (const int4*)dst);
    scan_onepass_kernel<<<NBLK_SCAN, 1024>>>();
    fill_kernel<<<FILL_GRID + 2, 256>>>((const int4*)src, (const int4*)dst, W1, W2);

    gemm1_mma_kernel<<<GB, 256, sm1>>>(x, (__half*)p_t1);

    gather128_relu_kernel<<<(NN * 32 + 255) / 256, 256>>>(
        (const __half*)p_t1, b1, (__half*)p_h);

    gemm2_mma_kernel<<<GB, 256, sm2>>>((const __half*)p_h, (__half*)p_t2);

    gather64_kernel<<<(NN * 32 + 255) / 256, 256>>>(
        (const __half*)p_t2, b2, out);
}

// round 16
// speedup vs baseline: 1.0910x; 1.0463x over previous
#include <cuda_runtime.h>
#include <cuda_fp16.h>

#define NN 100000
#define NE 1600000
#define F_HID 128
#define F_CLS 64
#define NBLK_SCAN 98               // ceil(NN/1024)
#define GB ((NN + 127) / 128)      // 128-row tiles = 782
#define ASTRIDE 136                // halfs per smem row (272B, LDSM conflict-free)
#define BSTRIDE 72                 // halfs per smem row for 64-wide W2 (144B)
#define CNT_GRID ((NE / 4 + 255) / 256)    // 1563 edge blocks
#define XCV_BLOCKS 592                      // X-convert blocks appended to count
#define FILL_GRID ((NE / 4 + 255) / 256)

// ---- scratch (device globals; no allocs allowed) ----
__device__ int    g_cnt[2 * NN + 256];
__device__ int    g_row_ptr[NN + 1];
__device__ int    g_epos[NE];
__device__ int    g_csr_src[NE];
__device__ float  g_norm_in[NN];
__device__ float  g_norm_out[NN];
__device__ __half g_w1h[128 * F_HID];   // fp16 copy of W1
__device__ __half g_w2h[128 * F_CLS];   // fp16 copy of W2
__device__ __half g_xh[(size_t)NN * F_HID];   // fp16 copy of x
__device__ __half g_t1[(size_t)NN * F_HID];
__device__ __half g_h [(size_t)NN * F_HID];
__device__ __half g_t2[(size_t)NN * F_CLS];

#define CNT_IN   (g_cnt)
#define CNT_OUT  (g_cnt + NN)
#define SCAN_VAL (g_cnt + 2 * NN)
#define SCAN_FLG (g_cnt + 2 * NN + 128)

// ---- fp16 vector load helpers ----
__device__ __forceinline__ void ldg_h4_f(const __half* p, float2& lo, float2& hi) {
    uint2 raw = __ldg((const uint2*)p);
    lo = __half22float2(*(const __half2*)&raw.x);
    hi = __half22float2(*(const __half2*)&raw.y);
}
__device__ __forceinline__ float2 ldg_h2_f(const __half* p) {
    unsigned int raw = __ldg((const unsigned int*)p);
    return __half22float2(*(const __half2*)&raw);
}

__device__ __forceinline__ int warp_incl_scan(int x, int lane) {
#pragma unroll
    for (int o = 1; o < 32; o <<= 1) {
        int y = __shfl_up_sync(0xffffffffu, x, o);
        if (lane >= o) x += y;
    }
    return x;
}

// ===========================================================================
// CSR build (+ X fp16 convert fused as extra blocks)
// ===========================================================================
__global__ __launch_bounds__(256) void count_kernel(const int4* __restrict__ src4,
                                                    const int4* __restrict__ dst4,
                                                    const float* __restrict__ X) {
    if (blockIdx.x >= CNT_GRID) {
        // X fp32 -> fp16 (NN*128 = 12.8M floats = 3.2M float4)
        const int n4 = NN * 128 / 4;
        int i0 = (blockIdx.x - CNT_GRID) * 256 + threadIdx.x;
        for (int i = i0; i < n4; i += XCV_BLOCKS * 256) {
            float4 v = __ldg(((const float4*)X) + i);
            __half2 h01 = __floats2half2_rn(v.x, v.y);
            __half2 h23 = __floats2half2_rn(v.z, v.w);
            uint2 u = make_uint2(*(unsigned*)&h01, *(unsigned*)&h23);
            ((uint2*)g_xh)[i] = u;
        }
        return;
    }
    int i = blockIdx.x * blockDim.x + threadIdx.x;
    if (i < NE / 4) {
        int4 s = __ldg(src4 + i);
        int4 d = __ldg(dst4 + i);
        atomicAdd(&CNT_OUT[s.x], 1); atomicAdd(&CNT_OUT[s.y], 1);
        atomicAdd(&CNT_OUT[s.z], 1); atomicAdd(&CNT_OUT[s.w], 1);
        int4 p;
        p.x = atomicAdd(&CNT_IN[d.x], 1);
        p.y = atomicAdd(&CNT_IN[d.y], 1);
        p.z = atomicAdd(&CNT_IN[d.z], 1);
        p.w = atomicAdd(&CNT_IN[d.w], 1);
        ((int4*)g_epos)[i] = p;
    }
}

// Single-pass scan with aggregate lookback (98 resident blocks).
__global__ __launch_bounds__(1024) void scan_onepass_kernel() {
    __shared__ int ws[32];
    __shared__ int s_base;
    int t = threadIdx.x, lane = t & 31, wid = t >> 5;
    int bid = blockIdx.x;

    int i = bid * 1024 + t;
    int v = (i < NN) ? CNT_IN[i] : 0;
    int x = warp_incl_scan(v, lane);
    if (lane == 31) ws[wid] = x;
    __syncthreads();
    if (wid == 0) ws[lane] = warp_incl_scan(ws[lane], lane);
    __syncthreads();
    int incl = x + (wid ? ws[wid - 1] : 0);
    int total = ws[31];

    if (t == 0) {
        SCAN_VAL[bid] = total;
        __threadfence();
        ((volatile int*)SCAN_FLG)[bid] = 1;
    }
    if (wid == 0) {
        int p = 0;
        for (int j = lane; j < bid; j += 32) {
            while (((volatile int*)SCAN_FLG)[j] == 0) { }
            p += ((volatile int*)SCAN_VAL)[j];
        }
        p = __reduce_add_sync(0xffffffffu, p);
        if (lane == 0) s_base = p;
    }
    __syncthreads();

    if (i < NN) {
        g_row_ptr[i] = incl - v + s_base;
        g_norm_in[i]  = rsqrtf(fmaxf((float)v, 1.0f));
        g_norm_out[i] = rsqrtf(fmaxf((float)CNT_OUT[i], 1.0f));
    }
    if (bid == 0 && t == 0) g_row_ptr[NN] = NE;
}

// fill: pure scatter, no atomics; two tail blocks convert W1/W2 -> fp16.
__global__ __launch_bounds__(256) void fill_kernel(const int4* __restrict__ src4,
                                                   const int4* __restrict__ dst4,
                                                   const float* __restrict__ W1,
                                                   const float* __restrict__ W2) {
    if (blockIdx.x == FILL_GRID) {        // W2 fp32 -> fp16
        int t = threadIdx.x;
        for (int i = t; i < 128 * F_CLS / 4; i += 256) {
            float4 v = __ldg(((const float4*)W2) + i);
            __half2 h01 = __floats2half2_rn(v.x, v.y);
            __half2 h23 = __floats2half2_rn(v.z, v.w);
            uint2 u = make_uint2(*(unsigned*)&h01, *(unsigned*)&h23);
            ((uint2*)g_w2h)[i] = u;
        }
        return;
    }
    if (blockIdx.x == FILL_GRID + 1) {    // W1 fp32 -> fp16
        int t = threadIdx.x;
        for (int i = t; i < 128 * F_HID / 4; i += 256) {
            float4 v = __ldg(((const float4*)W1) + i);
            __half2 h01 = __floats2half2_rn(v.x, v.y);
            __half2 h23 = __floats2half2_rn(v.z, v.w);
            uint2 u = make_uint2(*(unsigned*)&h01, *(unsigned*)&h23);
            ((uint2*)g_w1h)[i] = u;
        }
        return;
    }
    int i = blockIdx.x * blockDim.x + threadIdx.x;
    if (i < NE / 4) {
        int4 s = __ldg(src4 + i);
        int4 d = __ldg(dst4 + i);
        int4 p = ((const int4*)g_epos)[i];
        g_csr_src[__ldg(g_row_ptr + d.x) + p.x] = s.x;
        g_csr_src[__ldg(g_row_ptr + d.y) + p.y] = s.y;
        g_csr_src[__ldg(g_row_ptr + d.z) + p.z] = s.z;
        g_csr_src[__ldg(g_row_ptr + d.w) + p.w] = s.w;
    }
}

// ===========================================================================
// gemm1 (HMMA): t1[row] = half( (xh[row] @ W1h) * norm_out[row] )
// Pure uint4-copy staging (X pre-converted), coalesced staged epilogue.
// ===========================================================================
__global__ __launch_bounds__(256)
void gemm1_mma_kernel(__half* __restrict__ Y) {
    extern __shared__ __half hsm[];
    __half* A_s = hsm;                    // [128][ASTRIDE]
    __half* B_s = hsm + 128 * ASTRIDE;    // [128][ASTRIDE]

    const int tid = threadIdx.x;
    const int row0 = blockIdx.x * 128;

    // W1h -> B_s : 128 rows x 16 uint4
    for (int i = tid; i < 128 * 16; i += 256) {
        int k = i >> 4, c = i & 15;
        uint4 u = __ldg(((const uint4*)g_w1h) + i);
        *((uint4*)(B_s + k * ASTRIDE + c * 8)) = u;
    }
    // Xh tile -> A_s : 128 rows x 16 uint4
    const bool full = (row0 + 128 <= NN);
    for (int i = tid; i < 128 * 16; i += 256) {
        int r = i >> 4, c = i & 15;
        int row = row0 + r;
        uint4 u = (full || row < NN)
            ? __ldg(((const uint4*)(g_xh + (size_t)row * 128)) + c)
            : make_uint4(0u, 0u, 0u, 0u);
        *((uint4*)(A_s + r * ASTRIDE + c * 8)) = u;
    }
    __syncthreads();

    const int w = tid >> 5, lane = tid & 31;
    const int mrow = w * 16;

    float acc[16][4];
#pragma unroll
    for (int t = 0; t < 16; t++)
#pragma unroll
        for (int j = 0; j < 4; j++) acc[t][j] = 0.f;

#pragma unroll
    for (int ks = 0; ks < 8; ks++) {
        const int k0 = ks * 16;
        unsigned a0, a1, a2, a3;
        {
            const __half* pa = A_s + (mrow + (lane & 15)) * ASTRIDE
                             + k0 + (lane >> 4) * 8;
            unsigned addr = (unsigned)__cvta_generic_to_shared(pa);
            asm volatile("ldmatrix.sync.aligned.m8n8.x4.shared.b16 "
                         "{%0,%1,%2,%3}, [%4];"
                         : "=r"(a0), "=r"(a1), "=r"(a2), "=r"(a3) : "r"(addr));
        }
#pragma unroll
        for (int nt = 0; nt < 8; nt++) {
            unsigned b0, b1, b2, b3;
            const __half* pb = B_s + (k0 + (lane & 15)) * ASTRIDE
                             + nt * 16 + (lane >> 4) * 8;
            unsigned addr = (unsigned)__cvta_generic_to_shared(pb);
            asm volatile("ldmatrix.sync.aligned.m8n8.x4.trans.shared.b16 "
                         "{%0,%1,%2,%3}, [%4];"
                         : "=r"(b0), "=r"(b1), "=r"(b2), "=r"(b3) : "r"(addr));
            asm volatile("mma.sync.aligned.m16n8k16.row.col.f32.f16.f16.f32 "
                         "{%0,%1,%2,%3},{%4,%5,%6,%7},{%8,%9},{%0,%1,%2,%3};"
                         : "+f"(acc[nt*2][0]), "+f"(acc[nt*2][1]),
                           "+f"(acc[nt*2][2]), "+f"(acc[nt*2][3])
                         : "r"(a0), "r"(a1), "r"(a2), "r"(a3),
                           "r"(b0), "r"(b1));
            asm volatile("mma.sync.aligned.m16n8k16.row.col.f32.f16.f16.f32 "
                         "{%0,%1,%2,%3},{%4,%5,%6,%7},{%8,%9},{%0,%1,%2,%3};"
                         : "+f"(acc[nt*2+1][0]), "+f"(acc[nt*2+1][1]),
                           "+f"(acc[nt*2+1][2]), "+f"(acc[nt*2+1][3])
                         : "r"(a0), "r"(a1), "r"(a2), "r"(a3),
                           "r"(b2), "r"(b3));
        }
    }

    // Staged epilogue: scatter scaled fp16 into A_s, then coalesced STG.128.
    __syncthreads();
    {
        const int rla = mrow + (lane >> 2);
        const int rlb = rla + 8;
        const float nsa = (row0 + rla < NN) ? __ldg(g_norm_out + row0 + rla) : 0.f;
        const float nsb = (row0 + rlb < NN) ? __ldg(g_norm_out + row0 + rlb) : 0.f;
        const int cbase = (lane & 3) * 2;
#pragma unroll
        for (int t = 0; t < 16; t++) {
            int c = t * 8 + cbase;
            *((__half2*)(A_s + rla * ASTRIDE + c)) =
                __floats2half2_rn(acc[t][0] * nsa, acc[t][1] * nsa);
            *((__half2*)(A_s + rlb * ASTRIDE + c)) =
                __floats2half2_rn(acc[t][2] * nsb, acc[t][3] * nsb);
        }
    }
    __syncthreads();
    for (int i = tid; i < 128 * 16; i += 256) {
        int r = i >> 4, ch = i & 15;
        int row = row0 + r;
        if (row < NN) {
            uint4 u = *((const uint4*)(A_s + r * ASTRIDE + ch * 8));
            ((uint4*)(Y + (size_t)row * 128))[ch] = u;
        }
    }
}

// ===========================================================================
// gather128+relu: h[n] = half( relu(norm_in[n]*sum t1[csr] + b1) )
// ===========================================================================
__global__ __launch_bounds__(256)
void gather128_relu_kernel(const __half* __restrict__ T,
                           const float* __restrict__ b,
                           __half* __restrict__ out) {
    int w = (blockIdx.x * blockDim.x + threadIdx.x) >> 5;
    int lane = threadIdx.x & 31;
    if (w >= NN) return;
    int beg = g_row_ptr[w], end = g_row_ptr[w + 1];
    float4 acc = make_float4(0.f, 0.f, 0.f, 0.f);
    int i = beg;
    for (; i + 3 < end; i += 4) {
        int s0 = __ldg(g_csr_src + i),     s1 = __ldg(g_csr_src + i + 1);
        int s2 = __ldg(g_csr_src + i + 2), s3 = __ldg(g_csr_src + i + 3);
        float2 a0, c0, a1, c1, a2, c2, a3, c3;
        ldg_h4_f(T + (size_t)s0 * 128 + lane * 4, a0, c0);
        ldg_h4_f(T + (size_t)s1 * 128 + lane * 4, a1, c1);
        ldg_h4_f(T + (size_t)s2 * 128 + lane * 4, a2, c2);
        ldg_h4_f(T + (size_t)s3 * 128 + lane * 4, a3, c3);
        acc.x += (a0.x + a1.x) + (a2.x + a3.x);
        acc.y += (a0.y + a1.y) + (a2.y + a3.y);
        acc.z += (c0.x + c1.x) + (c2.x + c3.x);
        acc.w += (c0.y + c1.y) + (c2.y + c3.y);
    }
    for (; i < end; i++) {
        int s0 = __ldg(g_csr_src + i);
        float2 a0, c0;
        ldg_h4_f(T + (size_t)s0 * 128 + lane * 4, a0, c0);
        acc.x += a0.x; acc.y += a0.y; acc.z += c0.x; acc.w += c0.y;
    }
    float nd = g_norm_in[w];
    float4 bb = __ldg(((const float4*)b) + lane);
    float hx = fmaxf(fmaf(acc.x, nd, bb.x), 0.f);
    float hy = fmaxf(fmaf(acc.y, nd, bb.y), 0.f);
    float hz = fmaxf(fmaf(acc.z, nd, bb.z), 0.f);
    float hw = fmaxf(fmaf(acc.w, nd, bb.w), 0.f);
    __half2 o0 = __floats2half2_rn(hx, hy);
    __half2 o1 = __floats2half2_rn(hz, hw);
    uint2 u = make_uint2(*(unsigned*)&o0, *(unsigned*)&o1);
    ((uint2*)(out + (size_t)w * 128))[lane] = u;
}

// ===========================================================================
// gemm2 (HMMA): t2[row] = half( (h[row] @ W2h) * norm_out[row] )   N=64
// ===========================================================================
__global__ __launch_bounds__(256)
void gemm2_mma_kernel(const __half* __restrict__ H,
                      __half* __restrict__ Y) {
    extern __shared__ __half hsm[];
    __half* A_s = hsm;                    // [128][ASTRIDE]
    __half* B_s = hsm + 128 * ASTRIDE;    // [128][BSTRIDE]

    const int tid = threadIdx.x;
    const int row0 = blockIdx.x * 128;

    for (int i = tid; i < 128 * 8; i += 256) {
        int k = i >> 3, c = i & 7;
        uint4 u = __ldg(((const uint4*)g_w2h) + i);
        *((uint4*)(B_s + k * BSTRIDE + c * 8)) = u;
    }
    const bool full = (row0 + 128 <= NN);
    for (int i = tid; i < 128 * 16; i += 256) {
        int r = i >> 4, c = i & 15;
        int row = row0 + r;
        uint4 u = (full || row < NN)
            ? __ldg(((const uint4*)(H + (size_t)row * 128)) + c)
            : make_uint4(0u, 0u, 0u, 0u);
        *((uint4*)(A_s + r * ASTRIDE + c * 8)) = u;
    }
    __syncthreads();

    const int w = tid >> 5, lane = tid & 31;
    const int mrow = w * 16;

    float acc[8][4];
#pragma unroll
    for (int t = 0; t < 8; t++)
#pragma unroll
        for (int j = 0; j < 4; j++) acc[t][j] = 0.f;

#pragma unroll
    for (int ks = 0; ks < 8; ks++) {
        const int k0 = ks * 16;
        unsigned a0, a1, a2, a3;
        {
            const __half* pa = A_s + (mrow + (lane & 15)) * ASTRIDE
                             + k0 + (lane >> 4) * 8;
            unsigned addr = (unsigned)__cvta_generic_to_shared(pa);
            asm volatile("ldmatrix.sync.aligned.m8n8.x4.shared.b16 "
                         "{%0,%1,%2,%3}, [%4];"
                         : "=r"(a0), "=r"(a1), "=r"(a2), "=r"(a3) : "r"(addr));
        }
#pragma unroll
        for (int nt = 0; nt < 4; nt++) {
            unsigned b0, b1, b2, b3;
            const __half* pb = B_s + (k0 + (lane & 15)) * BSTRIDE
                             + nt * 16 + (lane >> 4) * 8;
            unsigned addr = (unsigned)__cvta_generic_to_shared(pb);
            asm volatile("ldmatrix.sync.aligned.m8n8.x4.trans.shared.b16 "
                         "{%0,%1,%2,%3}, [%4];"
                         : "=r"(b0), "=r"(b1), "=r"(b2), "=r"(b3) : "r"(addr));
            asm volatile("mma.sync.aligned.m16n8k16.row.col.f32.f16.f16.f32 "
                         "{%0,%1,%2,%3},{%4,%5,%6,%7},{%8,%9},{%0,%1,%2,%3};"
                         : "+f"(acc[nt*2][0]), "+f"(acc[nt*2][1]),
                           "+f"(acc[nt*2][2]), "+f"(acc[nt*2][3])
                         : "r"(a0), "r"(a1), "r"(a2), "r"(a3),
                           "r"(b0), "r"(b1));
            asm volatile("mma.sync.aligned.m16n8k16.row.col.f32.f16.f16.f32 "
                         "{%0,%1,%2,%3},{%4,%5,%6,%7},{%8,%9},{%0,%1,%2,%3};"
                         : "+f"(acc[nt*2+1][0]), "+f"(acc[nt*2+1][1]),
                           "+f"(acc[nt*2+1][2]), "+f"(acc[nt*2+1][3])
                         : "r"(a0), "r"(a1), "r"(a2), "r"(a3),
                           "r"(b2), "r"(b3));
        }
    }

    __syncthreads();
    {
        const int rla = mrow + (lane >> 2);
        const int rlb = rla + 8;
        const float nsa = (row0 + rla < NN) ? __ldg(g_norm_out + row0 + rla) : 0.f;
        const float nsb = (row0 + rlb < NN) ? __ldg(g_norm_out + row0 + rlb) : 0.f;
        const int cbase = (lane & 3) * 2;
#pragma unroll
        for (int t = 0; t < 8; t++) {
            int c = t * 8 + cbase;
            *((__half2*)(A_s + rla * ASTRIDE + c)) =
                __floats2half2_rn(acc[t][0] * nsa, acc[t][1] * nsa);
            *((__half2*)(A_s + rlb * ASTRIDE + c)) =
                __floats2half2_rn(acc[t][2] * nsb, acc[t][3] * nsb);
        }
    }
    __syncthreads();
    for (int i = tid; i < 128 * 8; i += 256) {
        int r = i >> 3, ch = i & 7;
        int row = row0 + r;
        if (row < NN) {
            uint4 u = *((const uint4*)(A_s + r * ASTRIDE + ch * 8));
            ((uint4*)(Y + (size_t)row * 64))[ch] = u;
        }
    }
}

// ===========================================================================
// Final gather: out[n] = norm_in[n] * sum t2[csr] + b2
// ===========================================================================
__global__ __launch_bounds__(256)
void gather64_kernel(const __half* __restrict__ T,
                     const float* __restrict__ b,
                     float* __restrict__ out) {
    int w = (blockIdx.x * blockDim.x + threadIdx.x) >> 5;
    int lane = threadIdx.x & 31;
    if (w >= NN) return;
    int beg = g_row_ptr[w], end = g_row_ptr[w + 1];
    float2 acc = make_float2(0.f, 0.f);
    int i = beg;
    for (; i + 3 < end; i += 4) {
        int s0 = __ldg(g_csr_src + i),     s1 = __ldg(g_csr_src + i + 1);
        int s2 = __ldg(g_csr_src + i + 2), s3 = __ldg(g_csr_src + i + 3);
        float2 f0 = ldg_h2_f(T + (size_t)s0 * 64 + lane * 2);
        float2 f1 = ldg_h2_f(T + (size_t)s1 * 64 + lane * 2);
        float2 f2 = ldg_h2_f(T + (size_t)s2 * 64 + lane * 2);
        float2 f3 = ldg_h2_f(T + (size_t)s3 * 64 + lane * 2);
        acc.x += (f0.x + f1.x) + (f2.x + f3.x);
        acc.y += (f0.y + f1.y) + (f2.y + f3.y);
    }
    for (; i < end; i++) {
        int s0 = __ldg(g_csr_src + i);
        float2 f0 = ldg_h2_f(T + (size_t)s0 * 64 + lane * 2);
        acc.x += f0.x; acc.y += f0.y;
    }
    float nd = g_norm_in[w];
    float2 bb = __ldg(((const float2*)b) + lane);
    float2 o;
    o.x = fmaf(acc.x, nd, bb.x);
    o.y = fmaf(acc.y, nd, bb.y);
    ((float2*)(out + (size_t)w * 64))[lane] = o;
}

// ===========================================================================
extern "C" void kernel_launch(void* const* d_in, const int* in_sizes, int n_in,
                              void* d_out, int out_size) {
    const float* x   = (const float*)d_in[0];
    const int*   src = (const int*)d_in[1];
    const int*   dst = (const int*)d_in[2];
    const float* W1  = (const float*)d_in[3];
    const float* b1  = (const float*)d_in[4];
    const float* W2  = (const float*)d_in[5];
    const float* b2  = (const float*)d_in[6];
    float* out = (float*)d_out;

    void *p_t1, *p_t2, *p_h, *p_cnt;
    cudaGetSymbolAddress(&p_t1, g_t1);
    cudaGetSymbolAddress(&p_t2, g_t2);
    cudaGetSymbolAddress(&p_h,  g_h);
    cudaGetSymbolAddress(&p_cnt, g_cnt);

    size_t sm1 = (size_t)(2 * 128 * ASTRIDE) * sizeof(__half);   // ~68KB
    cudaFuncSetAttribute(gemm1_mma_kernel,
                         cudaFuncAttributeMaxDynamicSharedMemorySize, (int)sm1);
    size_t sm2 = (size_t)(128 * ASTRIDE + 128 * BSTRIDE) * sizeof(__half); // ~44KB
    cudaFuncSetAttribute(gemm2_mma_kernel,
                         cudaFuncAttributeMaxDynamicSharedMemorySize, (int)sm2);

    cudaMemsetAsync(p_cnt, 0, (2 * NN + 256) * sizeof(int));
    count_kernel<<<CNT_GRID + XCV_BLOCKS, 256>>>(
        (const int4*)src, (const int4*)dst, x);
    scan_onepass_kernel<<<NBLK_SCAN, 1024>>>();
    fill_kernel<<<FILL_GRID + 2, 256>>>((const int4*)src, (const int4*)dst, W1, W2);

    gemm1_mma_kernel<<<GB, 256, sm1>>>((__half*)p_t1);

    gather128_relu_kernel<<<(NN * 32 + 255) / 256, 256>>>(
        (const __half*)p_t1, b1, (__half*)p_h);

    gemm2_mma_kernel<<<GB, 256, sm2>>>((const __half*)p_h, (__half*)p_t2);

    gather64_kernel<<<(NN * 32 + 255) / 256, 256>>>(
        (const __half*)p_t2, b2, out);
}

// round 17
// speedup vs baseline: 1.1466x; 1.0510x over previous
#include <cuda_runtime.h>
#include <cuda_fp16.h>

#define NN 100000
#define NE 1600000
#define F_HID 128
#define F_CLS 64
#define NBLK_SCAN 98               // ceil(NN/1024)
#define GB ((NN + 127) / 128)      // 128-row tiles = 782
#define ASTRIDE 136                // halfs per smem row (272B, LDSM conflict-free)
#define BSTRIDE 72                 // halfs per smem row for 64-wide W2 (144B)
#define CNT_GRID ((NE / 4 + 255) / 256)    // 1563 edge blocks
#define XCV_BLOCKS 592                      // X-convert blocks appended to count
#define FILL_GRID ((NE / 4 + 255) / 256)

// ---- scratch (device globals; no allocs allowed) ----
__device__ int    g_cnt[2 * NN + 256];
__device__ int    g_row_ptr[NN + 1];
__device__ int    g_epos[NE];
__device__ int    g_csr_src[NE];
__device__ float  g_norm_in[NN];
__device__ float  g_norm_out[NN];
__device__ __half g_w1h[128 * F_HID];   // fp16 copy of W1
__device__ __half g_w2h[128 * F_CLS];   // fp16 copy of W2
__device__ __half g_xh[(size_t)NN * F_HID];   // fp16 copy of x
__device__ __half g_t1[(size_t)NN * F_HID];
__device__ __half g_h [(size_t)NN * F_HID];
__device__ __half g_t2[(size_t)NN * F_CLS];

#define CNT_IN   (g_cnt)
#define CNT_OUT  (g_cnt + NN)
#define SCAN_VAL (g_cnt + 2 * NN)
#define SCAN_FLG (g_cnt + 2 * NN + 128)

// ---- cp.async helpers ----
__device__ __forceinline__ void cp16(const __half* smem_dst, const void* gsrc) {
    unsigned s = (unsigned)__cvta_generic_to_shared(smem_dst);
    asm volatile("cp.async.cg.shared.global [%0], [%1], 16;"
                 :: "r"(s), "l"(gsrc) : "memory");
}
__device__ __forceinline__ void cp16_pred(const __half* smem_dst, const void* gsrc,
                                          int sz) {
    unsigned s = (unsigned)__cvta_generic_to_shared(smem_dst);
    asm volatile("cp.async.cg.shared.global [%0], [%1], 16, %2;"
                 :: "r"(s), "l"(gsrc), "r"(sz) : "memory");
}
__device__ __forceinline__ void cp_wait_all() {
    asm volatile("cp.async.commit_group;\n\tcp.async.wait_group 0;" ::: "memory");
}

// ---- fp16 vector load helpers ----
__device__ __forceinline__ void ldg_h4_f(const __half* p, float2& lo, float2& hi) {
    uint2 raw = __ldg((const uint2*)p);
    lo = __half22float2(*(const __half2*)&raw.x);
    hi = __half22float2(*(const __half2*)&raw.y);
}
__device__ __forceinline__ float2 ldg_h2_f(const __half* p) {
    unsigned int raw = __ldg((const unsigned int*)p);
    return __half22float2(*(const __half2*)&raw);
}

__device__ __forceinline__ int warp_incl_scan(int x, int lane) {
#pragma unroll
    for (int o = 1; o < 32; o <<= 1) {
        int y = __shfl_up_sync(0xffffffffu, x, o);
        if (lane >= o) x += y;
    }
    return x;
}

// ===========================================================================
// CSR build (+ X fp16 convert fused as extra blocks)
// ===========================================================================
__global__ __launch_bounds__(256) void count_kernel(const int4* __restrict__ src4,
                                                    const int4* __restrict__ dst4,
                                                    const float* __restrict__ X) {
    if (blockIdx.x >= CNT_GRID) {
        const int n4 = NN * 128 / 4;
        int i0 = (blockIdx.x - CNT_GRID) * 256 + threadIdx.x;
        for (int i = i0; i < n4; i += XCV_BLOCKS * 256) {
            float4 v = __ldg(((const float4*)X) + i);
            __half2 h01 = __floats2half2_rn(v.x, v.y);
            __half2 h23 = __floats2half2_rn(v.z, v.w);
            uint2 u = make_uint2(*(unsigned*)&h01, *(unsigned*)&h23);
            ((uint2*)g_xh)[i] = u;
        }
        return;
    }
    int i = blockIdx.x * blockDim.x + threadIdx.x;
    if (i < NE / 4) {
        int4 s = __ldg(src4 + i);
        int4 d = __ldg(dst4 + i);
        atomicAdd(&CNT_OUT[s.x], 1); atomicAdd(&CNT_OUT[s.y], 1);
        atomicAdd(&CNT_OUT[s.z], 1); atomicAdd(&CNT_OUT[s.w], 1);
        int4 p;
        p.x = atomicAdd(&CNT_IN[d.x], 1);
        p.y = atomicAdd(&CNT_IN[d.y], 1);
        p.z = atomicAdd(&CNT_IN[d.z], 1);
        p.w = atomicAdd(&CNT_IN[d.w], 1);
        ((int4*)g_epos)[i] = p;
    }
}

// Single-pass scan with aggregate lookback (98 resident blocks).
__global__ __launch_bounds__(1024) void scan_onepass_kernel() {
    __shared__ int ws[32];
    __shared__ int s_base;
    int t = threadIdx.x, lane = t & 31, wid = t >> 5;
    int bid = blockIdx.x;

    int i = bid * 1024 + t;
    int v = (i < NN) ? CNT_IN[i] : 0;
    int x = warp_incl_scan(v, lane);
    if (lane == 31) ws[wid] = x;
    __syncthreads();
    if (wid == 0) ws[lane] = warp_incl_scan(ws[lane], lane);
    __syncthreads();
    int incl = x + (wid ? ws[wid - 1] : 0);
    int total = ws[31];

    if (t == 0) {
        SCAN_VAL[bid] = total;
        __threadfence();
        ((volatile int*)SCAN_FLG)[bid] = 1;
    }
    if (wid == 0) {
        int p = 0;
        for (int j = lane; j < bid; j += 32) {
            while (((volatile int*)SCAN_FLG)[j] == 0) { }
            p += ((volatile int*)SCAN_VAL)[j];
        }
        p = __reduce_add_sync(0xffffffffu, p);
        if (lane == 0) s_base = p;
    }
    __syncthreads();

    if (i < NN) {
        g_row_ptr[i] = incl - v + s_base;
        g_norm_in[i]  = rsqrtf(fmaxf((float)v, 1.0f));
        g_norm_out[i] = rsqrtf(fmaxf((float)CNT_OUT[i], 1.0f));
    }
    if (bid == 0 && t == 0) g_row_ptr[NN] = NE;
}

// fill: pure scatter, no atomics; two tail blocks convert W1/W2 -> fp16.
__global__ __launch_bounds__(256) void fill_kernel(const int4* __restrict__ src4,
                                                   const int4* __restrict__ dst4,
                                                   const float* __restrict__ W1,
                                                   const float* __restrict__ W2) {
    if (blockIdx.x == FILL_GRID) {        // W2 fp32 -> fp16
        int t = threadIdx.x;
        for (int i = t; i < 128 * F_CLS / 4; i += 256) {
            float4 v = __ldg(((const float4*)W2) + i);
            __half2 h01 = __floats2half2_rn(v.x, v.y);
            __half2 h23 = __floats2half2_rn(v.z, v.w);
            uint2 u = make_uint2(*(unsigned*)&h01, *(unsigned*)&h23);
            ((uint2*)g_w2h)[i] = u;
        }
        return;
    }
    if (blockIdx.x == FILL_GRID + 1) {    // W1 fp32 -> fp16
        int t = threadIdx.x;
        for (int i = t; i < 128 * F_HID / 4; i += 256) {
            float4 v = __ldg(((const float4*)W1) + i);
            __half2 h01 = __floats2half2_rn(v.x, v.y);
            __half2 h23 = __floats2half2_rn(v.z, v.w);
            uint2 u = make_uint2(*(unsigned*)&h01, *(unsigned*)&h23);
            ((uint2*)g_w1h)[i] = u;
        }
        return;
    }
    int i = blockIdx.x * blockDim.x + threadIdx.x;
    if (i < NE / 4) {
        int4 s = __ldg(src4 + i);
        int4 d = __ldg(dst4 + i);
        int4 p = ((const int4*)g_epos)[i];
        g_csr_src[__ldg(g_row_ptr + d.x) + p.x] = s.x;
        g_csr_src[__ldg(g_row_ptr + d.y) + p.y] = s.y;
        g_csr_src[__ldg(g_row_ptr + d.z) + p.z] = s.z;
        g_csr_src[__ldg(g_row_ptr + d.w) + p.w] = s.w;
    }
}

// ===========================================================================
// gemm1 (HMMA): t1[row] = half( (xh[row] @ W1h) * norm_out[row] )
// cp.async staging (no reg round-trip), coalesced staged epilogue.
// ===========================================================================
__global__ __launch_bounds__(256, 3)
void gemm1_mma_kernel(__half* __restrict__ Y) {
    extern __shared__ __half hsm[];
    __half* A_s = hsm;                    // [128][ASTRIDE]
    __half* B_s = hsm + 128 * ASTRIDE;    // [128][ASTRIDE]

    const int tid = threadIdx.x;
    const int row0 = blockIdx.x * 128;

    // W1h -> B_s via cp.async
    for (int i = tid; i < 128 * 16; i += 256) {
        int k = i >> 4, c = i & 15;
        cp16(B_s + k * ASTRIDE + c * 8, ((const uint4*)g_w1h) + i);
    }
    // Xh tile -> A_s via cp.async (zero-fill OOB rows)
    for (int i = tid; i < 128 * 16; i += 256) {
        int r = i >> 4, c = i & 15;
        int row = row0 + r;
        int rc = row < NN ? row : NN - 1;
        cp16_pred(A_s + r * ASTRIDE + c * 8,
                  (const uint4*)(g_xh + (size_t)rc * 128) + c,
                  row < NN ? 16 : 0);
    }
    cp_wait_all();
    __syncthreads();

    const int w = tid >> 5, lane = tid & 31;
    const int mrow = w * 16;

    float acc[16][4];
#pragma unroll
    for (int t = 0; t < 16; t++)
#pragma unroll
        for (int j = 0; j < 4; j++) acc[t][j] = 0.f;

#pragma unroll
    for (int ks = 0; ks < 8; ks++) {
        const int k0 = ks * 16;
        unsigned a0, a1, a2, a3;
        {
            const __half* pa = A_s + (mrow + (lane & 15)) * ASTRIDE
                             + k0 + (lane >> 4) * 8;
            unsigned addr = (unsigned)__cvta_generic_to_shared(pa);
            asm volatile("ldmatrix.sync.aligned.m8n8.x4.shared.b16 "
                         "{%0,%1,%2,%3}, [%4];"
                         : "=r"(a0), "=r"(a1), "=r"(a2), "=r"(a3) : "r"(addr));
        }
#pragma unroll
        for (int nt = 0; nt < 8; nt++) {
            unsigned b0, b1, b2, b3;
            const __half* pb = B_s + (k0 + (lane & 15)) * ASTRIDE
                             + nt * 16 + (lane >> 4) * 8;
            unsigned addr = (unsigned)__cvta_generic_to_shared(pb);
            asm volatile("ldmatrix.sync.aligned.m8n8.x4.trans.shared.b16 "
                         "{%0,%1,%2,%3}, [%4];"
                         : "=r"(b0), "=r"(b1), "=r"(b2), "=r"(b3) : "r"(addr));
            asm volatile("mma.sync.aligned.m16n8k16.row.col.f32.f16.f16.f32 "
                         "{%0,%1,%2,%3},{%4,%5,%6,%7},{%8,%9},{%0,%1,%2,%3};"
                         : "+f"(acc[nt*2][0]), "+f"(acc[nt*2][1]),
                           "+f"(acc[nt*2][2]), "+f"(acc[nt*2][3])
                         : "r"(a0), "r"(a1), "r"(a2), "r"(a3),
                           "r"(b0), "r"(b1));
            asm volatile("mma.sync.aligned.m16n8k16.row.col.f32.f16.f16.f32 "
                         "{%0,%1,%2,%3},{%4,%5,%6,%7},{%8,%9},{%0,%1,%2,%3};"
                         : "+f"(acc[nt*2+1][0]), "+f"(acc[nt*2+1][1]),
                           "+f"(acc[nt*2+1][2]), "+f"(acc[nt*2+1][3])
                         : "r"(a0), "r"(a1), "r"(a2), "r"(a3),
                           "r"(b2), "r"(b3));
        }
    }

    // Staged epilogue
    __syncthreads();
    {
        const int rla = mrow + (lane >> 2);
        const int rlb = rla + 8;
        const float nsa = (row0 + rla < NN) ? __ldg(g_norm_out + row0 + rla) : 0.f;
        const float nsb = (row0 + rlb < NN) ? __ldg(g_norm_out + row0 + rlb) : 0.f;
        const int cbase = (lane & 3) * 2;
#pragma unroll
        for (int t = 0; t < 16; t++) {
            int c = t * 8 + cbase;
            *((__half2*)(A_s + rla * ASTRIDE + c)) =
                __floats2half2_rn(acc[t][0] * nsa, acc[t][1] * nsa);
            *((__half2*)(A_s + rlb * ASTRIDE + c)) =
                __floats2half2_rn(acc[t][2] * nsb, acc[t][3] * nsb);
        }
    }
    __syncthreads();
    for (int i = tid; i < 128 * 16; i += 256) {
        int r = i >> 4, ch = i & 15;
        int row = row0 + r;
        if (row < NN) {
            uint4 u = *((const uint4*)(A_s + r * ASTRIDE + ch * 8));
            ((uint4*)(Y + (size_t)row * 128))[ch] = u;
        }
    }
}

// ===========================================================================
// gather128+relu: h[n] = half( relu(norm_in[n]*sum t1[csr] + b1) )
// ===========================================================================
__global__ __launch_bounds__(256)
void gather128_relu_kernel(const __half* __restrict__ T,
                           const float* __restrict__ b,
                           __half* __restrict__ out) {
    int w = (blockIdx.x * blockDim.x + threadIdx.x) >> 5;
    int lane = threadIdx.x & 31;
    if (w >= NN) return;
    int beg = g_row_ptr[w], end = g_row_ptr[w + 1];
    float4 acc = make_float4(0.f, 0.f, 0.f, 0.f);
    int i = beg;
    for (; i + 3 < end; i += 4) {
        int s0 = __ldg(g_csr_src + i),     s1 = __ldg(g_csr_src + i + 1);
        int s2 = __ldg(g_csr_src + i + 2), s3 = __ldg(g_csr_src + i + 3);
        float2 a0, c0, a1, c1, a2, c2, a3, c3;
        ldg_h4_f(T + (size_t)s0 * 128 + lane * 4, a0, c0);
        ldg_h4_f(T + (size_t)s1 * 128 + lane * 4, a1, c1);
        ldg_h4_f(T + (size_t)s2 * 128 + lane * 4, a2, c2);
        ldg_h4_f(T + (size_t)s3 * 128 + lane * 4, a3, c3);
        acc.x += (a0.x + a1.x) + (a2.x + a3.x);
        acc.y += (a0.y + a1.y) + (a2.y + a3.y);
        acc.z += (c0.x + c1.x) + (c2.x + c3.x);
        acc.w += (c0.y + c1.y) + (c2.y + c3.y);
    }
    for (; i < end; i++) {
        int s0 = __ldg(g_csr_src + i);
        float2 a0, c0;
        ldg_h4_f(T + (size_t)s0 * 128 + lane * 4, a0, c0);
        acc.x += a0.x; acc.y += a0.y; acc.z += c0.x; acc.w += c0.y;
    }
    float nd = g_norm_in[w];
    float4 bb = __ldg(((const float4*)b) + lane);
    float hx = fmaxf(fmaf(acc.x, nd, bb.x), 0.f);
    float hy = fmaxf(fmaf(acc.y, nd, bb.y), 0.f);
    float hz = fmaxf(fmaf(acc.z, nd, bb.z), 0.f);
    float hw = fmaxf(fmaf(acc.w, nd, bb.w), 0.f);
    __half2 o0 = __floats2half2_rn(hx, hy);
    __half2 o1 = __floats2half2_rn(hz, hw);
    uint2 u = make_uint2(*(unsigned*)&o0, *(unsigned*)&o1);
    ((uint2*)(out + (size_t)w * 128))[lane] = u;
}

// ===========================================================================
// gemm2 (HMMA): t2[row] = half( (h[row] @ W2h) * norm_out[row] )   N=64
// ===========================================================================
__global__ __launch_bounds__(256)
void gemm2_mma_kernel(const __half* __restrict__ H,
                      __half* __restrict__ Y) {
    extern __shared__ __half hsm[];
    __half* A_s = hsm;                    // [128][ASTRIDE]
    __half* B_s = hsm + 128 * ASTRIDE;    // [128][BSTRIDE]

    const int tid = threadIdx.x;
    const int row0 = blockIdx.x * 128;

    for (int i = tid; i < 128 * 8; i += 256) {
        int k = i >> 3, c = i & 7;
        cp16(B_s + k * BSTRIDE + c * 8, ((const uint4*)g_w2h) + i);
    }
    for (int i = tid; i < 128 * 16; i += 256) {
        int r = i >> 4, c = i & 15;
        int row = row0 + r;
        int rc = row < NN ? row : NN - 1;
        cp16_pred(A_s + r * ASTRIDE + c * 8,
                  (const uint4*)(H + (size_t)rc * 128) + c,
                  row < NN ? 16 : 0);
    }
    cp_wait_all();
    __syncthreads();

    const int w = tid >> 5, lane = tid & 31;
    const int mrow = w * 16;

    float acc[8][4];
#pragma unroll
    for (int t = 0; t < 8; t++)
#pragma unroll
        for (int j = 0; j < 4; j++) acc[t][j] = 0.f;

#pragma unroll
    for (int ks = 0; ks < 8; ks++) {
        const int k0 = ks * 16;
        unsigned a0, a1, a2, a3;
        {
            const __half* pa = A_s + (mrow + (lane & 15)) * ASTRIDE
                             + k0 + (lane >> 4) * 8;
            unsigned addr = (unsigned)__cvta_generic_to_shared(pa);
            asm volatile("ldmatrix.sync.aligned.m8n8.x4.shared.b16 "
                         "{%0,%1,%2,%3}, [%4];"
                         : "=r"(a0), "=r"(a1), "=r"(a2), "=r"(a3) : "r"(addr));
        }
#pragma unroll
        for (int nt = 0; nt < 4; nt++) {
            unsigned b0, b1, b2, b3;
            const __half* pb = B_s + (k0 + (lane & 15)) * BSTRIDE
                             + nt * 16 + (lane >> 4) * 8;
            unsigned addr = (unsigned)__cvta_generic_to_shared(pb);
            asm volatile("ldmatrix.sync.aligned.m8n8.x4.trans.shared.b16 "
                         "{%0,%1,%2,%3}, [%4];"
                         : "=r"(b0), "=r"(b1), "=r"(b2), "=r"(b3) : "r"(addr));
            asm volatile("mma.sync.aligned.m16n8k16.row.col.f32.f16.f16.f32 "
                         "{%0,%1,%2,%3},{%4,%5,%6,%7},{%8,%9},{%0,%1,%2,%3};"
                         : "+f"(acc[nt*2][0]), "+f"(acc[nt*2][1]),
                           "+f"(acc[nt*2][2]), "+f"(acc[nt*2][3])
                         : "r"(a0), "r"(a1), "r"(a2), "r"(a3),
                           "r"(b0), "r"(b1));
            asm volatile("mma.sync.aligned.m16n8k16.row.col.f32.f16.f16.f32 "
                         "{%0,%1,%2,%3},{%4,%5,%6,%7},{%8,%9},{%0,%1,%2,%3};"
                         : "+f"(acc[nt*2+1][0]), "+f"(acc[nt*2+1][1]),
                           "+f"(acc[nt*2+1][2]), "+f"(acc[nt*2+1][3])
                         : "r"(a0), "r"(a1), "r"(a2), "r"(a3),
                           "r"(b2), "r"(b3));
        }
    }

    __syncthreads();
    {
        const int rla = mrow + (lane >> 2);
        const int rlb = rla + 8;
        const float nsa = (row0 + rla < NN) ? __ldg(g_norm_out + row0 + rla) : 0.f;
        const float nsb = (row0 + rlb < NN) ? __ldg(g_norm_out + row0 + rlb) : 0.f;
        const int cbase = (lane & 3) * 2;
#pragma unroll
        for (int t = 0; t < 8; t++) {
            int c = t * 8 + cbase;
            *((__half2*)(A_s + rla * ASTRIDE + c)) =
                __floats2half2_rn(acc[t][0] * nsa, acc[t][1] * nsa);
            *((__half2*)(A_s + rlb * ASTRIDE + c)) =
                __floats2half2_rn(acc[t][2] * nsb, acc[t][3] * nsb);
        }
    }
    __syncthreads();
    for (int i = tid; i < 128 * 8; i += 256) {
        int r = i >> 3, ch = i & 7;
        int row = row0 + r;
        if (row < NN) {
            uint4 u = *((const uint4*)(A_s + r * ASTRIDE + ch * 8));
            ((uint4*)(Y + (size_t)row * 64))[ch] = u;
        }
    }
}

// ===========================================================================
// Final gather: out[n] = norm_in[n] * sum t2[csr] + b2
// ===========================================================================
__global__ __launch_bounds__(256)
void gather64_kernel(const __half* __restrict__ T,
                     const float* __restrict__ b,
                     float* __restrict__ out) {
    int w = (blockIdx.x * blockDim.x + threadIdx.x) >> 5;
    int lane = threadIdx.x & 31;
    if (w >= NN) return;
    int beg = g_row_ptr[w], end = g_row_ptr[w + 1];
    float2 acc = make_float2(0.f, 0.f);
    int i = beg;
    for (; i + 3 < end; i += 4) {
        int s0 = __ldg(g_csr_src + i),     s1 = __ldg(g_csr_src + i + 1);
        int s2 = __ldg(g_csr_src + i + 2), s3 = __ldg(g_csr_src + i + 3);
        float2 f0 = ldg_h2_f(T + (size_t)s0 * 64 + lane * 2);
        float2 f1 = ldg_h2_f(T + (size_t)s1 * 64 + lane * 2);
        float2 f2 = ldg_h2_f(T + (size_t)s2 * 64 + lane * 2);
        float2 f3 = ldg_h2_f(T + (size_t)s3 * 64 + lane * 2);
        acc.x += (f0.x + f1.x) + (f2.x + f3.x);
        acc.y += (f0.y + f1.y) + (f2.y + f3.y);
    }
    for (; i < end; i++) {
        int s0 = __ldg(g_csr_src + i);
        float2 f0 = ldg_h2_f(T + (size_t)s0 * 64 + lane * 2);
        acc.x += f0.x; acc.y += f0.y;
    }
    float nd = g_norm_in[w];
    float2 bb = __ldg(((const float2*)b) + lane);
    float2 o;
    o.x = fmaf(acc.x, nd, bb.x);
    o.y = fmaf(acc.y, nd, bb.y);
    ((float2*)(out + (size_t)w * 64))[lane] = o;
}

// ===========================================================================
extern "C" void kernel_launch(void* const* d_in, const int* in_sizes, int n_in,
                              void* d_out, int out_size) {
    const float* x   = (const float*)d_in[0];
    const int*   src = (const int*)d_in[1];
    const int*   dst = (const int*)d_in[2];
    const float* W1  = (const float*)d_in[3];
    const float* b1  = (const float*)d_in[4];
    const float* W2  = (const float*)d_in[5];
    const float* b2  = (const float*)d_in[6];
    float* out = (float*)d_out;

    void *p_t1, *p_t2, *p_h, *p_cnt;
    cudaGetSymbolAddress(&p_t1, g_t1);
    cudaGetSymbolAddress(&p_t2, g_t2);
    cudaGetSymbolAddress(&p_h,  g_h);
    cudaGetSymbolAddress(&p_cnt, g_cnt);

    size_t sm1 = (size_t)(2 * 128 * ASTRIDE) * sizeof(__half);   // ~68KB
    cudaFuncSetAttribute(gemm1_mma_kernel,
                         cudaFuncAttributeMaxDynamicSharedMemorySize, (int)sm1);
    size_t sm2 = (size_t)(128 * ASTRIDE + 128 * BSTRIDE) * sizeof(__half); // ~44KB
    cudaFuncSetAttribute(gemm2_mma_kernel,
                         cudaFuncAttributeMaxDynamicSharedMemorySize, (int)sm2);

    cudaMemsetAsync(p_cnt, 0, (2 * NN + 256) * sizeof(int));
    count_kernel<<<CNT_GRID + XCV_BLOCKS, 256>>>(
        (const int4*)src, (const int4*)dst, x);
    scan_onepass_kernel<<<NBLK_SCAN, 1024>>>();
    fill_kernel<<<FILL_GRID + 2, 256>>>((const int4*)src, (const int4*)dst, W1, W2);

    gemm1_mma_kernel<<<GB, 256, sm1>>>((__half*)p_t1);

    gather128_relu_kernel<<<(NN * 32 + 255) / 256, 256>>>(
        (const __half*)p_t1, b1, (__half*)p_h);

    gemm2_mma_kernel<<<GB, 256, sm2>>>((const __half*)p_h, (__half*)p_t2);

    gather64_kernel<<<(NN * 32 + 255) / 256, 256>>>(
        (const __half*)p_t2, b2, out);
}